// round 13
// baseline (speedup 1.0000x reference)
#include <cuda_runtime.h>
#include <cuda_fp16.h>
#include <math.h>
#include <stdint.h>

// ---------------- problem constants ----------------
constexpr int BB = 4, SSEQ = 2048, DD = 1024, FF = 4096;
constexpr int MM = BB * SSEQ;                 // 8192
constexpr long long BSD = (long long)MM * DD; // 8388608

// ---------------- scratch (device globals; no allocation) ----------------
__device__ __half g_xn_h[MM * DD];
__device__ __half g_gate[MM * DD];            // sigmoid(gate_pre), fp16
__device__ __half g_m[MM * DD];               // m = 1 - a, fp16 (bounded-error encoding)
__device__ __half g_cc_h[MM * 2 * DD];        // [conv | griffin_h] fp16
__device__ __half g_xnew_h[MM * DD];          // x + velocity_new, fp16
__device__ __half g_nm_h[MM * DD];
__device__ __half g_hd_h[MM * FF];
__device__ __half g_wt_h[12 * 1024 * 1024];
__device__ float  g_splam[DD];
// decoupled-lookback scan records: 64 chunks x (B*D) channels
constexpr int SCH = 64, SLEN = SSEQ / SCH;    // 64 chunks of 32
__device__ float2 g_recPH[BB * SCH * DD];     // (p, h) partial
__device__ float  g_recI [BB * SCH * DD];     // inclusive H

// ---------------- helpers ----------------
__device__ __forceinline__ uint32_t s2u(const void* p) {
    uint32_t a;
    asm("{ .reg .u64 t; cvta.to.shared.u64 t, %1; cvt.u32.u64 %0, t; }" : "=r"(a) : "l"(p));
    return a;
}
__device__ __forceinline__ void cpasync16(uint32_t saddr, const void* g) {
    asm volatile("cp.async.cg.shared.global [%0], [%1], 16;" :: "r"(saddr), "l"(g));
}
__device__ __forceinline__ void cp_commit() {
    asm volatile("cp.async.commit_group;" ::: "memory");
}
template <int N>
__device__ __forceinline__ void cp_wait() {
    asm volatile("cp.async.wait_group %0;" :: "n"(N) : "memory");
}
__device__ __forceinline__ void ldsm4(uint32_t* r, uint32_t addr) {
    asm volatile("ldmatrix.sync.aligned.m8n8.x4.shared.b16 {%0,%1,%2,%3}, [%4];"
                 : "=r"(r[0]), "=r"(r[1]), "=r"(r[2]), "=r"(r[3]) : "r"(addr));
}
__device__ __forceinline__ void mma16816(float* d, const uint32_t* a, const uint32_t* b) {
    asm volatile(
        "mma.sync.aligned.m16n8k16.row.col.f32.f16.f16.f32 "
        "{%0,%1,%2,%3}, {%4,%5,%6,%7}, {%8,%9}, {%0,%1,%2,%3};"
        : "+f"(d[0]), "+f"(d[1]), "+f"(d[2]), "+f"(d[3])
        : "r"(a[0]), "r"(a[1]), "r"(a[2]), "r"(a[3]), "r"(b[0]), "r"(b[1]));
}
__device__ __forceinline__ float2 ldcg2(const float2* p) {
    float2 v;
    asm volatile("ld.global.cg.v2.f32 {%0,%1}, [%2];" : "=f"(v.x), "=f"(v.y) : "l"(p));
    return v;
}
__device__ __forceinline__ void stcg2(float2* p, float2 v) {
    asm volatile("st.global.cg.v2.f32 [%0], {%1,%2};" :: "l"(p), "f"(v.x), "f"(v.y) : "memory");
}
__device__ __forceinline__ float ldcg1(const float* p) {
    float v;
    asm volatile("ld.global.cg.f32 %0, [%1];" : "=f"(v) : "l"(p));
    return v;
}
__device__ __forceinline__ void stcg1(float* p, float v) {
    asm volatile("st.global.cg.f32 [%0], %1;" :: "l"(p), "f"(v) : "memory");
}

// ------- weight transpose (block-offset param so it can be split) -------
__global__ void transpose_all(const float* __restrict__ Wg, const float* __restrict__ Wa,
                              const float* __restrict__ Wo, const float* __restrict__ W1,
                              const float* __restrict__ W2, __half* __restrict__ out,
                              int boff) {
    int b = blockIdx.x + boff;
    const float* W;
    int K, N;
    size_t off;
    int tile;
    if (b < 1024)      { W = Wg; K = 1024; N = 1024; off = 0;               tile = b; }
    else if (b < 2048) { W = Wa; K = 1024; N = 1024; off = (size_t)1 << 20; tile = b - 1024; }
    else if (b < 4096) { W = Wo; K = 2048; N = 1024; off = (size_t)2 << 20; tile = b - 2048; }
    else if (b < 8192) { W = W1; K = 1024; N = 4096; off = (size_t)4 << 20; tile = b - 4096; }
    else               { W = W2; K = 4096; N = 1024; off = (size_t)8 << 20; tile = b - 8192; }
    int ntn = N >> 5;
    int n0 = (tile % ntn) * 32, k0 = (tile / ntn) * 32;
    __half* oh = out + off;

    __shared__ float t[32][33];
    int tid = threadIdx.x;
    #pragma unroll
    for (int i = 0; i < 4; i++) {
        int idx = tid + i * 256;
        int kr = idx >> 5, nc = idx & 31;
        t[kr][nc] = W[(size_t)(k0 + kr) * N + n0 + nc];
    }
    __syncthreads();
    #pragma unroll
    for (int i = 0; i < 2; i++) {
        int idx = tid + i * 256;
        int nr = idx >> 4, kp = idx & 15;
        float v0 = t[kp * 2][nr], v1 = t[kp * 2 + 1][nr];
        size_t o = (size_t)(n0 + nr) * K + k0 + kp * 2;
        *(__half2*)(oh + o) = __halves2half2(__float2half_rn(v0), __float2half_rn(v1));
    }
}

// ---------------- rmsnorm (fp32 in) -> fp16 ----------------
__global__ void rmsnorm_h(const float* __restrict__ in, const float* __restrict__ w,
                          __half* __restrict__ oh) {
    int row = blockIdx.x;
    const float4* ip = (const float4*)(in + (size_t)row * DD);
    float4 v = ip[threadIdx.x];
    float ss = v.x * v.x + v.y * v.y + v.z * v.z + v.w * v.w;
    #pragma unroll
    for (int o = 16; o > 0; o >>= 1) ss += __shfl_xor_sync(0xffffffffu, ss, o);
    __shared__ float ws[8];
    int lane = threadIdx.x & 31, wid = threadIdx.x >> 5;
    if (lane == 0) ws[wid] = ss;
    __syncthreads();
    if (wid == 0) {
        float s = (lane < 8) ? ws[lane] : 0.f;
        #pragma unroll
        for (int o = 4; o > 0; o >>= 1) s += __shfl_xor_sync(0xffffffffu, s, o);
        if (lane == 0) ws[0] = s;
    }
    __syncthreads();
    float rms = rsqrtf(ws[0] * (1.0f / DD) + 1e-6f);
    float4 wv = ((const float4*)w)[threadIdx.x];
    size_t o0 = (size_t)row * DD + threadIdx.x * 4;
    *(__half2*)(oh + o0)     = __halves2half2(__float2half_rn(v.x * rms * wv.x),
                                              __float2half_rn(v.y * rms * wv.y));
    *(__half2*)(oh + o0 + 2) = __halves2half2(__float2half_rn(v.z * rms * wv.z),
                                              __float2half_rn(v.w * rms * wv.w));
}

// ---------------- rmsnorm (fp16 in) -> fp16 ----------------
__global__ void rmsnorm_h16(const __half* __restrict__ in, const float* __restrict__ w,
                            __half* __restrict__ oh) {
    int row = blockIdx.x;
    const __half2* ip = (const __half2*)(in + (size_t)row * DD);
    __half2 h0 = ip[threadIdx.x * 2], h1 = ip[threadIdx.x * 2 + 1];
    float x0 = __half2float(h0.x), x1 = __half2float(h0.y);
    float x2 = __half2float(h1.x), x3 = __half2float(h1.y);
    float ss = x0 * x0 + x1 * x1 + x2 * x2 + x3 * x3;
    #pragma unroll
    for (int o = 16; o > 0; o >>= 1) ss += __shfl_xor_sync(0xffffffffu, ss, o);
    __shared__ float ws[8];
    int lane = threadIdx.x & 31, wid = threadIdx.x >> 5;
    if (lane == 0) ws[wid] = ss;
    __syncthreads();
    if (wid == 0) {
        float s = (lane < 8) ? ws[lane] : 0.f;
        #pragma unroll
        for (int o = 4; o > 0; o >>= 1) s += __shfl_xor_sync(0xffffffffu, s, o);
        if (lane == 0) ws[0] = s;
    }
    __syncthreads();
    float rms = rsqrtf(ws[0] * (1.0f / DD) + 1e-6f);
    float4 wv = ((const float4*)w)[threadIdx.x];
    size_t o0 = (size_t)row * DD + threadIdx.x * 4;
    *(__half2*)(oh + o0)     = __halves2half2(__float2half_rn(x0 * rms * wv.x),
                                              __float2half_rn(x1 * rms * wv.y));
    *(__half2*)(oh + o0 + 2) = __halves2half2(__float2half_rn(x2 * rms * wv.z),
                                              __float2half_rn(x3 * rms * wv.w));
}

// ------- prologue: clear lookback records + splam (runs on side stream) -------
__global__ void prologue(const float* __restrict__ lam) {
    int i = blockIdx.x * 256 + threadIdx.x;   // < BB*SCH*DD = 262144
    float nf = __int_as_float(0x7fffffff);
    g_recPH[i] = make_float2(nf, nf);
    g_recI[i] = nf;
    if (i < DD) {
        float l = lam[i];
        float sp = (l > 20.f) ? l : log1pf(expf(l));
        g_splam[i] = 8.0f * sp;
    }
}

// ------- single-pass scan: conv + u + chunk scan + decoupled lookback -------
__global__ void __launch_bounds__(256) gscan_one(const float* __restrict__ ck,
                                                 const float* __restrict__ cb) {
    extern __shared__ float2 au[];            // [SLEN][256]
    int tid = threadIdx.x;
    int bid = blockIdx.x;                     // ch*16 + b*4 + dblk
    int ch = bid >> 4;
    int b = (bid >> 2) & 3;
    int dblk = bid & 3;
    int d = dblk * 256 + tid;

    float4 kv = ((const float4*)ck)[d];
    float cbias = cb[d];

    long long r0 = (long long)b * SSEQ + ch * SLEN;
    long long xbase = r0 * DD + d;
    float xm1 = 0.f, xm2 = 0.f, xm3 = 0.f;
    if (ch > 0) {
        xm1 = __half2float(g_xn_h[xbase - DD]);
        xm2 = __half2float(g_xn_h[xbase - 2 * DD]);
        xm3 = __half2float(g_xn_h[xbase - 3 * DD]);
    }
    float p = 1.f, h = 0.f;
    #pragma unroll 4
    for (int t = 0; t < SLEN; t++) {
        long long i = xbase + (long long)t * DD;
        float xn = __half2float(g_xn_h[i]);
        float conv = cbias + kv.x * xn + kv.y * xm1 + kv.z * xm2 + kv.w * xm3;
        float gate = __half2float(g_gate[i]);
        float m = __half2float(g_m[i]);       // m = 1 - a, bounded-error encoding
        float a = 1.f - m;
        float u = sqrtf(fmaxf(m * (2.f - m), 0.f)) * gate * xn;
        g_cc_h[(r0 + t) * (2 * DD) + d] = __float2half_rn(conv);
        au[t * 256 + tid] = make_float2(a, u);
        p *= a;
        h = fmaf(a, h, u);
        xm3 = xm2; xm2 = xm1; xm1 = xn;
    }

    int recbase = b * SCH * DD + d;
    stcg2(&g_recPH[recbase + ch * DD], make_float2(p, h));

    float C = 0.f;
    if (ch > 0) {
        float accP = 1.f, accH = 0.f;
        int look = ch - 1;
        while (true) {
            float hi = ldcg1(&g_recI[recbase + look * DD]);
            if (!isnan(hi)) { C = fmaf(accP, hi, accH); break; }
            float2 ph = ldcg2(&g_recPH[recbase + look * DD]);
            if (!isnan(ph.x)) {
                accH = fmaf(accP, ph.y, accH);
                accP *= ph.x;
                if (--look < 0) { C = accH; break; }
            }
        }
    }
    stcg1(&g_recI[recbase + ch * DD], fmaf(p, C, h));

    h = C;
    #pragma unroll 4
    for (int t = 0; t < SLEN; t++) {
        float2 v = au[t * 256 + tid];
        h = fmaf(v.x, h, v.y);
        g_cc_h[(r0 + t) * (2 * DD) + DD + d] = __float2half_rn(h);
    }
}

// ------- HMMA GEMM: 128x128 tile, 8 warps, 64x32 warp tiles, BK=64 -------
// 3-stage cp.async (32 KB/stage), 2 CTAs/SM. grid: x = N-blocks, y = M-blocks.
// EPI: 1 mixer (xnew -> fp16 out2h); 2 gelu->fp16; 3 +bias + fp16 aux residual;
//      4 gating (gate->fp16 out2h, m=-expm1(-splam*sigmoid)->fp16 auxh, N-stride 1024)
constexpr int STG = 32768;           // A 16K | B 16K
constexpr int GEMM_SMEM = 3 * STG;   // 96 KB

template <int EPI>
__global__ void __launch_bounds__(256)
hgemm(const __half* __restrict__ Ah, const __half* __restrict__ Bh,
      float* __restrict__ C, int N, int K,
      const float* __restrict__ bias,
      const float* __restrict__ aux1, const float* __restrict__ aux2,
      const float* __restrict__ aux3,
      __half* __restrict__ out2h,
      __half* __restrict__ auxh) {
    extern __shared__ char sm[];
    uint32_t sb = s2u(sm);
    int tid = threadIdx.x;
    int lane = tid & 31, wid = tid >> 5;
    int wm = wid >> 2, wn = wid & 3;          // warp tile 64x32
    size_t mrow0 = (size_t)blockIdx.y * 128;
    size_t ncol0 = (size_t)blockIdx.x * 128;

    float acc[4][4][4];
    #pragma unroll
    for (int a = 0; a < 4; a++)
        #pragma unroll
        for (int b = 0; b < 4; b++)
            #pragma unroll
            for (int c = 0; c < 4; c++) acc[a][b][c] = 0.f;

    auto load_stage = [&](int s, int k0) {
        uint32_t base = sb + s * STG;
        #pragma unroll
        for (int i = 0; i < 4; i++) {
            int idx = tid + i * 256;
            int r = idx >> 3, c = idx & 7;
            uint32_t sw = r * 128 + ((c ^ (r & 7)) << 4);
            cpasync16(base + sw, Ah + (mrow0 + r) * K + k0 + c * 8);
            cpasync16(base + 16384 + sw, Bh + (ncol0 + r) * K + k0 + c * 8);
        }
    };

    const int KT = K >> 6;  // BK = 64
    load_stage(0, 0);
    cp_commit();
    load_stage(1, 64);
    cp_commit();

    for (int kt = 0; kt < KT; kt++) {
        if (kt + 1 < KT) cp_wait<1>(); else cp_wait<0>();
        __syncthreads();
        if (kt + 2 < KT) {
            int s = kt + 2;
            load_stage(s % 3, s << 6);
            cp_commit();
        }
        uint32_t base = sb + (kt % 3) * STG;
        #pragma unroll
        for (int kk = 0; kk < 4; kk++) {
            uint32_t ah[4][4], bh[2][4];
            int g = lane >> 3;
            int ar = (lane & 7) + ((g & 1) << 3);
            int ac = kk * 2 + (g >> 1);
            #pragma unroll
            for (int mi = 0; mi < 4; mi++) {
                int row = wm * 64 + mi * 16 + ar;
                uint32_t off = row * 128 + ((ac ^ (row & 7)) << 4);
                ldsm4(ah[mi], base + off);
            }
            int br = (lane & 7) + ((g >> 1) << 3);
            int bc = kk * 2 + (g & 1);
            #pragma unroll
            for (int ni = 0; ni < 2; ni++) {
                int row = wn * 32 + ni * 16 + br;
                uint32_t off = row * 128 + ((bc ^ (row & 7)) << 4);
                ldsm4(bh[ni], base + 16384 + off);
            }
            #pragma unroll
            for (int mi = 0; mi < 4; mi++)
                #pragma unroll
                for (int n8 = 0; n8 < 4; n8++)
                    mma16816(acc[mi][n8], ah[mi], &bh[n8 >> 1][(n8 & 1) * 2]);
        }
    }

    // ---------------- epilogue ----------------
    const float c0g = 0.7978845608028654f, c1g = 0.044715f;
    #pragma unroll
    for (int mi = 0; mi < 4; mi++) {
        #pragma unroll
        for (int n8 = 0; n8 < 4; n8++) {
            int col = (int)ncol0 + wn * 32 + n8 * 8 + (lane & 3) * 2;
            #pragma unroll
            for (int half_ = 0; half_ < 2; half_++) {
                size_t row = mrow0 + wm * 64 + mi * 16 + (lane >> 2) + half_ * 8;
                float v0 = acc[mi][n8][half_ * 2 + 0];
                float v1 = acc[mi][n8][half_ * 2 + 1];
                size_t off = row * N + col;
                if (EPI == 1) {
                    float2 bia = *(const float2*)(bias + col);
                    float2 lb  = *(const float2*)(aux3 + col);
                    float2 vel = *(const float2*)(aux1 + off);
                    float2 xv  = *(const float2*)(aux2 + off);
                    float vn0 = fmaf(1.f / (1.f + __expf(-lb.x)), vel.x, v0 + bia.x);
                    float vn1 = fmaf(1.f / (1.f + __expf(-lb.y)), vel.y, v1 + bia.y);
                    *(float2*)(C + off) = make_float2(vn0, vn1);
                    *(__half2*)(out2h + off) =
                        __halves2half2(__float2half_rn(xv.x + vn0), __float2half_rn(xv.y + vn1));
                } else if (EPI == 2) {
                    float2 bia = *(const float2*)(bias + col);
                    float t0 = v0 + bia.x, t1 = v1 + bia.y;
                    t0 = 0.5f * t0 * (1.f + tanhf(c0g * (t0 + c1g * t0 * t0 * t0)));
                    t1 = 0.5f * t1 * (1.f + tanhf(c0g * (t1 + c1g * t1 * t1 * t1)));
                    *(__half2*)(out2h + off) =
                        __halves2half2(__float2half_rn(t0), __float2half_rn(t1));
                } else if (EPI == 3) {
                    float2 bia = *(const float2*)(bias + col);
                    __half2 xn2 = *(const __half2*)(auxh + off);
                    *(float2*)(C + off) = make_float2(v0 + bia.x + __half2float(xn2.x),
                                                      v1 + bia.y + __half2float(xn2.y));
                } else {  // EPI == 4: gating. N==2048; tile stays in one half.
                    if (col < 1024) {
                        float s0 = 1.f / (1.f + __expf(-v0));
                        float s1 = 1.f / (1.f + __expf(-v1));
                        *(__half2*)(out2h + row * 1024 + col) =
                            __halves2half2(__float2half_rn(s0), __float2half_rn(s1));
                    } else {
                        int d = col - 1024;
                        float sp0 = aux3[d], sp1 = aux3[d + 1];
                        float sa0 = 1.f / (1.f + __expf(-v0));
                        float sa1 = 1.f / (1.f + __expf(-v1));
                        float m0 = -expm1f(-sp0 * sa0);   // m = 1 - a, no cancellation
                        float m1 = -expm1f(-sp1 * sa1);
                        *(__half2*)(auxh + row * 1024 + d) =
                            __halves2half2(__float2half_rn(m0), __float2half_rn(m1));
                    }
                }
            }
        }
    }
}

// ---------------- launch ----------------
extern "C" void kernel_launch(void* const* d_in, const int* in_sizes, int n_in,
                              void* d_out, int out_size) {
    const float* x          = (const float*)d_in[0];
    const float* velocity   = (const float*)d_in[1];
    const float* pre_norm_w = (const float*)d_in[2];
    const float* conv_k     = (const float*)d_in[3];
    const float* conv_b     = (const float*)d_in[4];
    const float* W_gate     = (const float*)d_in[5];
    const float* W_a        = (const float*)d_in[6];
    const float* lam        = (const float*)d_in[7];
    const float* W_out      = (const float*)d_in[8];
    const float* b_out      = (const float*)d_in[9];
    const float* log_beta   = (const float*)d_in[10];
    const float* ffn_norm_w = (const float*)d_in[11];
    const float* W_ff1      = (const float*)d_in[12];
    const float* b_ff1      = (const float*)d_in[13];
    const float* W_ff2      = (const float*)d_in[14];
    const float* b_ff2      = (const float*)d_in[15];

    float* out1    = (float*)d_out;
    float* out_vel = out1 + BSD;

    __half *p_xn_h, *p_gate, *p_m, *p_cc_h, *p_xnew_h, *p_nm_h, *p_hd_h, *p_wt_h;
    float *p_splam;
    cudaGetSymbolAddress((void**)&p_xn_h, g_xn_h);
    cudaGetSymbolAddress((void**)&p_gate, g_gate);
    cudaGetSymbolAddress((void**)&p_m, g_m);
    cudaGetSymbolAddress((void**)&p_cc_h, g_cc_h);
    cudaGetSymbolAddress((void**)&p_xnew_h, g_xnew_h);
    cudaGetSymbolAddress((void**)&p_nm_h, g_nm_h);
    cudaGetSymbolAddress((void**)&p_hd_h, g_hd_h);
    cudaGetSymbolAddress((void**)&p_wt_h, g_wt_h);
    cudaGetSymbolAddress((void**)&p_splam, g_splam);

    cudaFuncSetAttribute(hgemm<1>, cudaFuncAttributeMaxDynamicSharedMemorySize, GEMM_SMEM);
    cudaFuncSetAttribute(hgemm<2>, cudaFuncAttributeMaxDynamicSharedMemorySize, GEMM_SMEM);
    cudaFuncSetAttribute(hgemm<3>, cudaFuncAttributeMaxDynamicSharedMemorySize, GEMM_SMEM);
    cudaFuncSetAttribute(hgemm<4>, cudaFuncAttributeMaxDynamicSharedMemorySize, GEMM_SMEM);
    constexpr int SCAN_SMEM = SLEN * 256 * sizeof(float2);   // 64 KB
    cudaFuncSetAttribute(gscan_one, cudaFuncAttributeMaxDynamicSharedMemorySize, SCAN_SMEM);

    // side stream + fork/join events
    cudaStream_t s_side;
    cudaEvent_t ev_fork, ev_j1, ev_j2;
    cudaStreamCreateWithFlags(&s_side, cudaStreamNonBlocking);
    cudaEventCreateWithFlags(&ev_fork, cudaEventDisableTiming);
    cudaEventCreateWithFlags(&ev_j1, cudaEventDisableTiming);
    cudaEventCreateWithFlags(&ev_j2, cudaEventDisableTiming);

    const size_t OFF_GA = 0, OFF_OUT = (size_t)2 << 20,
                 OFF_FF1 = (size_t)4 << 20, OFF_FF2 = (size_t)8 << 20;

    // fork side branch: prologue + weight transposes (all off critical path)
    cudaEventRecord(ev_fork, 0);
    cudaStreamWaitEvent(s_side, ev_fork, 0);
    prologue<<<BB * SCH * DD / 256, 256, 0, s_side>>>(lam);
    transpose_all<<<2048, 256, 0, s_side>>>(W_gate, W_a, W_out, W_ff1, W_ff2, p_wt_h, 0);
    cudaEventRecord(ev_j1, s_side);
    transpose_all<<<10240, 256, 0, s_side>>>(W_gate, W_a, W_out, W_ff1, W_ff2, p_wt_h, 2048);
    cudaEventRecord(ev_j2, s_side);

    // main stream: pre-norm
    rmsnorm_h<<<MM, 256>>>(x, pre_norm_w, p_xn_h);

    // join 1: prologue + gate/a weights ready
    cudaStreamWaitEvent(0, ev_j1, 0);

    // fused gate+a GEMM (M=8192, N=2048, K=1024) with gating epilogue
    dim3 gGA(2048 / 128, MM / 128);
    hgemm<4><<<gGA, 256, GEMM_SMEM>>>(p_xn_h, p_wt_h + OFF_GA,
                                      nullptr, 2048, 1024,
                                      nullptr, nullptr, nullptr, p_splam, p_gate, p_m);

    // single-pass conv + gating + scan (decoupled lookback)
    gscan_one<<<BB * SCH * (DD / 256), 256, SCAN_SMEM>>>(conv_k, conv_b);

    // join 2: remaining weights ready
    cudaStreamWaitEvent(0, ev_j2, 0);

    // mixer GEMM (K=2048) + velocity + residual (xnew -> fp16)
    dim3 gD(1024 / 128, MM / 128);
    hgemm<1><<<gD, 256, GEMM_SMEM>>>(p_cc_h, p_wt_h + OFF_OUT,
                                     out_vel, 1024, 2048,
                                     b_out, velocity, x, log_beta, p_xnew_h, nullptr);

    // ffn norm (fp16 in)
    rmsnorm_h16<<<MM, 256>>>(p_xnew_h, ffn_norm_w, p_nm_h);

    // ff1 + gelu -> fp16 hidden (N=4096, K=1024)
    dim3 gF(4096 / 128, MM / 128);
    hgemm<2><<<gF, 256, GEMM_SMEM>>>(p_nm_h, p_wt_h + OFF_FF1,
                                     nullptr, 4096, 1024,
                                     b_ff1, nullptr, nullptr, nullptr, p_hd_h, nullptr);

    // ff2 + fp16 residual (K=4096) -> out1
    hgemm<3><<<gD, 256, GEMM_SMEM>>>(p_hd_h, p_wt_h + OFF_FF2,
                                     out1, 1024, 4096,
                                     b_ff2, nullptr, nullptr, nullptr, nullptr, p_xnew_h);
}

// round 15
// speedup vs baseline: 1.0121x; 1.0121x over previous
#include <cuda_runtime.h>
#include <cuda_fp16.h>
#include <math.h>
#include <stdint.h>

// ---------------- problem constants ----------------
constexpr int BB = 4, SSEQ = 2048, DD = 1024, FF = 4096;
constexpr int MM = BB * SSEQ;                 // 8192
constexpr long long BSD = (long long)MM * DD; // 8388608

// ---------------- scratch (device globals; no allocation) ----------------
__device__ __half g_xn_h[MM * DD];
__device__ __half g_gate[MM * DD];            // sigmoid(gate_pre), fp16
__device__ float  g_a[MM * DD];               // recurrence coefficient, fp32
__device__ __half g_cc_h[MM * 2 * DD];        // [conv | griffin_h] fp16
__device__ __half g_xnew_h[MM * DD];          // x + velocity_new, fp16
__device__ __half g_nm_h[MM * DD];
__device__ __half g_hd_h[MM * FF];
__device__ __half g_wt_h[12 * 1024 * 1024];
__device__ float  g_splam[DD];
// decoupled-lookback scan records: 64 chunks x (B*D) channels
constexpr int SCH = 64, SLEN = SSEQ / SCH;    // 64 chunks of 32
__device__ float2 g_recPH[BB * SCH * DD];     // (p, h) partial
__device__ float  g_recI [BB * SCH * DD];     // inclusive H

// ---------------- helpers ----------------
__device__ __forceinline__ uint32_t s2u(const void* p) {
    uint32_t a;
    asm("{ .reg .u64 t; cvta.to.shared.u64 t, %1; cvt.u32.u64 %0, t; }" : "=r"(a) : "l"(p));
    return a;
}
__device__ __forceinline__ void cpasync16(uint32_t saddr, const void* g) {
    asm volatile("cp.async.cg.shared.global [%0], [%1], 16;" :: "r"(saddr), "l"(g));
}
__device__ __forceinline__ void cp_commit() {
    asm volatile("cp.async.commit_group;" ::: "memory");
}
template <int N>
__device__ __forceinline__ void cp_wait() {
    asm volatile("cp.async.wait_group %0;" :: "n"(N) : "memory");
}
__device__ __forceinline__ void ldsm4(uint32_t* r, uint32_t addr) {
    asm volatile("ldmatrix.sync.aligned.m8n8.x4.shared.b16 {%0,%1,%2,%3}, [%4];"
                 : "=r"(r[0]), "=r"(r[1]), "=r"(r[2]), "=r"(r[3]) : "r"(addr));
}
__device__ __forceinline__ void mma16816(float* d, const uint32_t* a, const uint32_t* b) {
    asm volatile(
        "mma.sync.aligned.m16n8k16.row.col.f32.f16.f16.f32 "
        "{%0,%1,%2,%3}, {%4,%5,%6,%7}, {%8,%9}, {%0,%1,%2,%3};"
        : "+f"(d[0]), "+f"(d[1]), "+f"(d[2]), "+f"(d[3])
        : "r"(a[0]), "r"(a[1]), "r"(a[2]), "r"(a[3]), "r"(b[0]), "r"(b[1]));
}
__device__ __forceinline__ float2 ldcg2(const float2* p) {
    float2 v;
    asm volatile("ld.global.cg.v2.f32 {%0,%1}, [%2];" : "=f"(v.x), "=f"(v.y) : "l"(p));
    return v;
}
__device__ __forceinline__ void stcg2(float2* p, float2 v) {
    asm volatile("st.global.cg.v2.f32 [%0], {%1,%2};" :: "l"(p), "f"(v.x), "f"(v.y) : "memory");
}
__device__ __forceinline__ float ldcg1(const float* p) {
    float v;
    asm volatile("ld.global.cg.f32 %0, [%1];" : "=f"(v) : "l"(p));
    return v;
}
__device__ __forceinline__ void stcg1(float* p, float v) {
    asm volatile("st.global.cg.f32 [%0], %1;" :: "l"(p), "f"(v) : "memory");
}
__device__ __forceinline__ uint32_t h2u(__half2 h) {
    return *(uint32_t*)&h;
}

// ------- weight transpose (block-offset param so it can be split) -------
__global__ void transpose_all(const float* __restrict__ Wg, const float* __restrict__ Wa,
                              const float* __restrict__ Wo, const float* __restrict__ W1,
                              const float* __restrict__ W2, __half* __restrict__ out,
                              int boff) {
    int b = blockIdx.x + boff;
    const float* W;
    int K, N;
    size_t off;
    int tile;
    if (b < 1024)      { W = Wg; K = 1024; N = 1024; off = 0;               tile = b; }
    else if (b < 2048) { W = Wa; K = 1024; N = 1024; off = (size_t)1 << 20; tile = b - 1024; }
    else if (b < 4096) { W = Wo; K = 2048; N = 1024; off = (size_t)2 << 20; tile = b - 2048; }
    else if (b < 8192) { W = W1; K = 1024; N = 4096; off = (size_t)4 << 20; tile = b - 4096; }
    else               { W = W2; K = 4096; N = 1024; off = (size_t)8 << 20; tile = b - 8192; }
    int ntn = N >> 5;
    int n0 = (tile % ntn) * 32, k0 = (tile / ntn) * 32;
    __half* oh = out + off;

    __shared__ float t[32][33];
    int tid = threadIdx.x;
    #pragma unroll
    for (int i = 0; i < 4; i++) {
        int idx = tid + i * 256;
        int kr = idx >> 5, nc = idx & 31;
        t[kr][nc] = W[(size_t)(k0 + kr) * N + n0 + nc];
    }
    __syncthreads();
    #pragma unroll
    for (int i = 0; i < 2; i++) {
        int idx = tid + i * 256;
        int nr = idx >> 4, kp = idx & 15;
        float v0 = t[kp * 2][nr], v1 = t[kp * 2 + 1][nr];
        size_t o = (size_t)(n0 + nr) * K + k0 + kp * 2;
        *(__half2*)(oh + o) = __halves2half2(__float2half_rn(v0), __float2half_rn(v1));
    }
}

// ------- rmsnorm (fp32 in) -> fp16, warp-per-row (no smem, no block sync) -------
__global__ void __launch_bounds__(256) rmsnorm_h(const float* __restrict__ in,
                                                 const float* __restrict__ w,
                                                 __half* __restrict__ oh) {
    int lane = threadIdx.x & 31, wrp = threadIdx.x >> 5;
    int row = blockIdx.x * 8 + wrp;
    const float4* ip = (const float4*)(in + (size_t)row * DD);
    float4 v[8];
    float ss = 0.f;
    #pragma unroll
    for (int i = 0; i < 8; i++) {
        v[i] = ip[lane + i * 32];
        ss += v[i].x * v[i].x + v[i].y * v[i].y + v[i].z * v[i].z + v[i].w * v[i].w;
    }
    #pragma unroll
    for (int o = 16; o > 0; o >>= 1) ss += __shfl_xor_sync(0xffffffffu, ss, o);
    float rms = rsqrtf(ss * (1.0f / DD) + 1e-6f);
    #pragma unroll
    for (int i = 0; i < 8; i++) {
        float4 wv = ((const float4*)w)[lane + i * 32];
        __half2 h0 = __halves2half2(__float2half_rn(v[i].x * rms * wv.x),
                                    __float2half_rn(v[i].y * rms * wv.y));
        __half2 h1 = __halves2half2(__float2half_rn(v[i].z * rms * wv.z),
                                    __float2half_rn(v[i].w * rms * wv.w));
        *(uint2*)(oh + (size_t)row * DD + (lane + i * 32) * 4) = make_uint2(h2u(h0), h2u(h1));
    }
}

// ------- rmsnorm (fp16 in) -> fp16, warp-per-row -------
__global__ void __launch_bounds__(256) rmsnorm_h16(const __half* __restrict__ in,
                                                   const float* __restrict__ w,
                                                   __half* __restrict__ oh) {
    int lane = threadIdx.x & 31, wrp = threadIdx.x >> 5;
    int row = blockIdx.x * 8 + wrp;
    const float4* ip = (const float4*)(in + (size_t)row * DD);  // 8 halves per float4
    float4 raw[4];
    float xs[32];
    float ss = 0.f;
    #pragma unroll
    for (int i = 0; i < 4; i++) {
        raw[i] = ip[lane + i * 32];
        const __half2* hp = (const __half2*)&raw[i];
        #pragma unroll
        for (int j = 0; j < 4; j++) {
            float2 f = __half22float2(hp[j]);
            xs[i * 8 + j * 2] = f.x;
            xs[i * 8 + j * 2 + 1] = f.y;
            ss += f.x * f.x + f.y * f.y;
        }
    }
    #pragma unroll
    for (int o = 16; o > 0; o >>= 1) ss += __shfl_xor_sync(0xffffffffu, ss, o);
    float rms = rsqrtf(ss * (1.0f / DD) + 1e-6f);
    #pragma unroll
    for (int i = 0; i < 4; i++) {
        int e0 = (lane + i * 32) * 8;        // first element index of this 8-wide group
        uint32_t pk[4];
        #pragma unroll
        for (int j = 0; j < 4; j++) {
            float2 wv = ((const float2*)w)[e0 / 2 + j];
            __half2 h = __halves2half2(__float2half_rn(xs[i * 8 + j * 2] * rms * wv.x),
                                       __float2half_rn(xs[i * 8 + j * 2 + 1] * rms * wv.y));
            pk[j] = h2u(h);
        }
        *(uint4*)(oh + (size_t)row * DD + e0) = make_uint4(pk[0], pk[1], pk[2], pk[3]);
    }
}

// ------- prologue: clear lookback records + splam -------
__global__ void prologue(const float* __restrict__ lam) {
    int i = blockIdx.x * 256 + threadIdx.x;   // < BB*SCH*DD = 262144
    float nf = __int_as_float(0x7fffffff);
    g_recPH[i] = make_float2(nf, nf);
    g_recI[i] = nf;
    if (i < DD) {
        float l = lam[i];
        float sp = (l > 20.f) ? l : log1pf(expf(l));
        g_splam[i] = 8.0f * sp;
    }
}

// ------- single-pass scan: conv + u + chunk scan + decoupled lookback -------
__global__ void __launch_bounds__(256) gscan_one(const float* __restrict__ ck,
                                                 const float* __restrict__ cb) {
    extern __shared__ float2 au[];            // [SLEN][256]
    int tid = threadIdx.x;
    int bid = blockIdx.x;                     // ch*16 + b*4 + dblk
    int ch = bid >> 4;
    int b = (bid >> 2) & 3;
    int dblk = bid & 3;
    int d = dblk * 256 + tid;

    float4 kv = ((const float4*)ck)[d];
    float cbias = cb[d];

    long long r0 = (long long)b * SSEQ + ch * SLEN;
    long long xbase = r0 * DD + d;
    float xm1 = 0.f, xm2 = 0.f, xm3 = 0.f;
    if (ch > 0) {
        xm1 = __half2float(g_xn_h[xbase - DD]);
        xm2 = __half2float(g_xn_h[xbase - 2 * DD]);
        xm3 = __half2float(g_xn_h[xbase - 3 * DD]);
    }
    float p = 1.f, h = 0.f;
    #pragma unroll 4
    for (int t = 0; t < SLEN; t++) {
        long long i = xbase + (long long)t * DD;
        float xn = __half2float(g_xn_h[i]);
        float conv = cbias + kv.x * xn + kv.y * xm1 + kv.z * xm2 + kv.w * xm3;
        float gate = __half2float(g_gate[i]);
        float a = g_a[i];
        float u = sqrtf(fmaxf(1.f - a * a, 0.f)) * gate * xn;
        g_cc_h[(r0 + t) * (2 * DD) + d] = __float2half_rn(conv);
        au[t * 256 + tid] = make_float2(a, u);
        p *= a;
        h = fmaf(a, h, u);
        xm3 = xm2; xm2 = xm1; xm1 = xn;
    }

    int recbase = b * SCH * DD + d;
    stcg2(&g_recPH[recbase + ch * DD], make_float2(p, h));

    float C = 0.f;
    if (ch > 0) {
        float accP = 1.f, accH = 0.f;
        int look = ch - 1;
        while (true) {
            float hi = ldcg1(&g_recI[recbase + look * DD]);
            if (!isnan(hi)) { C = fmaf(accP, hi, accH); break; }
            float2 ph = ldcg2(&g_recPH[recbase + look * DD]);
            if (!isnan(ph.x)) {
                accH = fmaf(accP, ph.y, accH);
                accP *= ph.x;
                if (--look < 0) { C = accH; break; }
            }
        }
    }
    stcg1(&g_recI[recbase + ch * DD], fmaf(p, C, h));

    h = C;
    #pragma unroll 4
    for (int t = 0; t < SLEN; t++) {
        float2 v = au[t * 256 + tid];
        h = fmaf(v.x, h, v.y);
        g_cc_h[(r0 + t) * (2 * DD) + DD + d] = __float2half_rn(h);
    }
}

// ------- HMMA GEMM: 128x128 tile, 8 warps, 64x32 warp tiles, BK=64 -------
// 3-stage cp.async (32 KB/stage), 2 CTAs/SM. grid: x = N-blocks, y = M-blocks.
// EPI: 1 mixer (xnew -> fp16 out2h); 2 gelu->fp16; 3 +bias + fp16 aux residual;
//      4 gating (gate->fp16 auxh, a=exp(-splam*sigmoid)->fp32 C, N-stride 1024)
constexpr int STG = 32768;           // A 16K | B 16K
constexpr int GEMM_SMEM = 3 * STG;   // 96 KB

template <int EPI>
__global__ void __launch_bounds__(256)
hgemm(const __half* __restrict__ Ah, const __half* __restrict__ Bh,
      float* __restrict__ C, int N, int K,
      const float* __restrict__ bias,
      const float* __restrict__ aux1, const float* __restrict__ aux2,
      const float* __restrict__ aux3,
      __half* __restrict__ out2h,
      __half* __restrict__ auxh) {
    extern __shared__ char sm[];
    uint32_t sb = s2u(sm);
    int tid = threadIdx.x;
    int lane = tid & 31, wid = tid >> 5;
    int wm = wid >> 2, wn = wid & 3;          // warp tile 64x32
    size_t mrow0 = (size_t)blockIdx.y * 128;
    size_t ncol0 = (size_t)blockIdx.x * 128;

    float acc[4][4][4];
    #pragma unroll
    for (int a = 0; a < 4; a++)
        #pragma unroll
        for (int b = 0; b < 4; b++)
            #pragma unroll
            for (int c = 0; c < 4; c++) acc[a][b][c] = 0.f;

    auto load_stage = [&](int s, int k0) {
        uint32_t base = sb + s * STG;
        #pragma unroll
        for (int i = 0; i < 4; i++) {
            int idx = tid + i * 256;
            int r = idx >> 3, c = idx & 7;
            uint32_t sw = r * 128 + ((c ^ (r & 7)) << 4);
            cpasync16(base + sw, Ah + (mrow0 + r) * K + k0 + c * 8);
            cpasync16(base + 16384 + sw, Bh + (ncol0 + r) * K + k0 + c * 8);
        }
    };

    const int KT = K >> 6;  // BK = 64
    load_stage(0, 0);
    cp_commit();
    load_stage(1, 64);
    cp_commit();

    for (int kt = 0; kt < KT; kt++) {
        if (kt + 1 < KT) cp_wait<1>(); else cp_wait<0>();
        __syncthreads();
        if (kt + 2 < KT) {
            int s = kt + 2;
            load_stage(s % 3, s << 6);
            cp_commit();
        }
        uint32_t base = sb + (kt % 3) * STG;
        #pragma unroll
        for (int kk = 0; kk < 4; kk++) {
            uint32_t ah[4][4], bh[2][4];
            int g = lane >> 3;
            int ar = (lane & 7) + ((g & 1) << 3);
            int ac = kk * 2 + (g >> 1);
            #pragma unroll
            for (int mi = 0; mi < 4; mi++) {
                int row = wm * 64 + mi * 16 + ar;
                uint32_t off = row * 128 + ((ac ^ (row & 7)) << 4);
                ldsm4(ah[mi], base + off);
            }
            int br = (lane & 7) + ((g >> 1) << 3);
            int bc = kk * 2 + (g & 1);
            #pragma unroll
            for (int ni = 0; ni < 2; ni++) {
                int row = wn * 32 + ni * 16 + br;
                uint32_t off = row * 128 + ((bc ^ (row & 7)) << 4);
                ldsm4(bh[ni], base + 16384 + off);
            }
            #pragma unroll
            for (int mi = 0; mi < 4; mi++)
                #pragma unroll
                for (int n8 = 0; n8 < 4; n8++)
                    mma16816(acc[mi][n8], ah[mi], &bh[n8 >> 1][(n8 & 1) * 2]);
        }
    }

    // ---------------- epilogue ----------------
    const float c0g = 0.7978845608028654f, c1g = 0.044715f;
    #pragma unroll
    for (int mi = 0; mi < 4; mi++) {
        #pragma unroll
        for (int n8 = 0; n8 < 4; n8++) {
            int col = (int)ncol0 + wn * 32 + n8 * 8 + (lane & 3) * 2;
            #pragma unroll
            for (int half_ = 0; half_ < 2; half_++) {
                size_t row = mrow0 + wm * 64 + mi * 16 + (lane >> 2) + half_ * 8;
                float v0 = acc[mi][n8][half_ * 2 + 0];
                float v1 = acc[mi][n8][half_ * 2 + 1];
                size_t off = row * N + col;
                if (EPI == 1) {
                    float2 bia = *(const float2*)(bias + col);
                    float2 lb  = *(const float2*)(aux3 + col);
                    float2 vel = *(const float2*)(aux1 + off);
                    float2 xv  = *(const float2*)(aux2 + off);
                    float vn0 = fmaf(1.f / (1.f + __expf(-lb.x)), vel.x, v0 + bia.x);
                    float vn1 = fmaf(1.f / (1.f + __expf(-lb.y)), vel.y, v1 + bia.y);
                    *(float2*)(C + off) = make_float2(vn0, vn1);
                    *(__half2*)(out2h + off) =
                        __halves2half2(__float2half_rn(xv.x + vn0), __float2half_rn(xv.y + vn1));
                } else if (EPI == 2) {
                    float2 bia = *(const float2*)(bias + col);
                    float t0 = v0 + bia.x, t1 = v1 + bia.y;
                    t0 = 0.5f * t0 * (1.f + tanhf(c0g * (t0 + c1g * t0 * t0 * t0)));
                    t1 = 0.5f * t1 * (1.f + tanhf(c0g * (t1 + c1g * t1 * t1 * t1)));
                    *(__half2*)(out2h + off) =
                        __halves2half2(__float2half_rn(t0), __float2half_rn(t1));
                } else if (EPI == 3) {
                    float2 bia = *(const float2*)(bias + col);
                    __half2 xn2 = *(const __half2*)(auxh + off);
                    *(float2*)(C + off) = make_float2(v0 + bia.x + __half2float(xn2.x),
                                                      v1 + bia.y + __half2float(xn2.y));
                } else {  // EPI == 4: gating. N==2048; tile stays in one half.
                    if (col < 1024) {
                        float s0 = 1.f / (1.f + __expf(-v0));
                        float s1 = 1.f / (1.f + __expf(-v1));
                        *(__half2*)(auxh + row * 1024 + col) =
                            __halves2half2(__float2half_rn(s0), __float2half_rn(s1));
                    } else {
                        int d = col - 1024;
                        float sp0 = aux3[d], sp1 = aux3[d + 1];
                        float sa0 = 1.f / (1.f + __expf(-v0));
                        float sa1 = 1.f / (1.f + __expf(-v1));
                        float a0 = expf(-sp0 * sa0);
                        float a1 = expf(-sp1 * sa1);
                        *(float2*)(C + row * 1024 + d) = make_float2(a0, a1);
                    }
                }
            }
        }
    }
}

// ---------------- launch ----------------
extern "C" void kernel_launch(void* const* d_in, const int* in_sizes, int n_in,
                              void* d_out, int out_size) {
    const float* x          = (const float*)d_in[0];
    const float* velocity   = (const float*)d_in[1];
    const float* pre_norm_w = (const float*)d_in[2];
    const float* conv_k     = (const float*)d_in[3];
    const float* conv_b     = (const float*)d_in[4];
    const float* W_gate     = (const float*)d_in[5];
    const float* W_a        = (const float*)d_in[6];
    const float* lam        = (const float*)d_in[7];
    const float* W_out      = (const float*)d_in[8];
    const float* b_out      = (const float*)d_in[9];
    const float* log_beta   = (const float*)d_in[10];
    const float* ffn_norm_w = (const float*)d_in[11];
    const float* W_ff1      = (const float*)d_in[12];
    const float* b_ff1      = (const float*)d_in[13];
    const float* W_ff2      = (const float*)d_in[14];
    const float* b_ff2      = (const float*)d_in[15];

    float* out1    = (float*)d_out;
    float* out_vel = out1 + BSD;

    __half *p_xn_h, *p_gate, *p_cc_h, *p_xnew_h, *p_nm_h, *p_hd_h, *p_wt_h;
    float *p_a, *p_splam;
    cudaGetSymbolAddress((void**)&p_xn_h, g_xn_h);
    cudaGetSymbolAddress((void**)&p_gate, g_gate);
    cudaGetSymbolAddress((void**)&p_a, g_a);
    cudaGetSymbolAddress((void**)&p_cc_h, g_cc_h);
    cudaGetSymbolAddress((void**)&p_xnew_h, g_xnew_h);
    cudaGetSymbolAddress((void**)&p_nm_h, g_nm_h);
    cudaGetSymbolAddress((void**)&p_hd_h, g_hd_h);
    cudaGetSymbolAddress((void**)&p_wt_h, g_wt_h);
    cudaGetSymbolAddress((void**)&p_splam, g_splam);

    cudaFuncSetAttribute(hgemm<1>, cudaFuncAttributeMaxDynamicSharedMemorySize, GEMM_SMEM);
    cudaFuncSetAttribute(hgemm<2>, cudaFuncAttributeMaxDynamicSharedMemorySize, GEMM_SMEM);
    cudaFuncSetAttribute(hgemm<3>, cudaFuncAttributeMaxDynamicSharedMemorySize, GEMM_SMEM);
    cudaFuncSetAttribute(hgemm<4>, cudaFuncAttributeMaxDynamicSharedMemorySize, GEMM_SMEM);
    constexpr int SCAN_SMEM = SLEN * 256 * sizeof(float2);   // 64 KB
    cudaFuncSetAttribute(gscan_one, cudaFuncAttributeMaxDynamicSharedMemorySize, SCAN_SMEM);

    // side stream + fork/join events
    cudaStream_t s_side;
    cudaEvent_t ev_fork, ev_j1, ev_j2;
    cudaStreamCreateWithFlags(&s_side, cudaStreamNonBlocking);
    cudaEventCreateWithFlags(&ev_fork, cudaEventDisableTiming);
    cudaEventCreateWithFlags(&ev_j1, cudaEventDisableTiming);
    cudaEventCreateWithFlags(&ev_j2, cudaEventDisableTiming);

    const size_t OFF_GA = 0, OFF_OUT = (size_t)2 << 20,
                 OFF_FF1 = (size_t)4 << 20, OFF_FF2 = (size_t)8 << 20;

    // fork side branch: weight transposes
    cudaEventRecord(ev_fork, 0);
    cudaStreamWaitEvent(s_side, ev_fork, 0);
    transpose_all<<<2048, 256, 0, s_side>>>(W_gate, W_a, W_out, W_ff1, W_ff2, p_wt_h, 0);
    cudaEventRecord(ev_j1, s_side);
    transpose_all<<<10240, 256, 0, s_side>>>(W_gate, W_a, W_out, W_ff1, W_ff2, p_wt_h, 2048);
    cudaEventRecord(ev_j2, s_side);

    // main stream: pre-norm (warp-per-row) + prologue
    rmsnorm_h<<<MM / 8, 256>>>(x, pre_norm_w, p_xn_h);
    prologue<<<BB * SCH * DD / 256, 256>>>(lam);

    // join 1: gate/a weights ready
    cudaStreamWaitEvent(0, ev_j1, 0);

    // fused gate+a GEMM (M=8192, N=2048, K=1024) with gating epilogue
    dim3 gGA(2048 / 128, MM / 128);
    hgemm<4><<<gGA, 256, GEMM_SMEM>>>(p_xn_h, p_wt_h + OFF_GA,
                                      p_a, 2048, 1024,
                                      nullptr, nullptr, nullptr, p_splam, nullptr, p_gate);

    // single-pass conv + gating + scan (decoupled lookback)
    gscan_one<<<BB * SCH * (DD / 256), 256, SCAN_SMEM>>>(conv_k, conv_b);

    // join 2: remaining weights ready
    cudaStreamWaitEvent(0, ev_j2, 0);

    // mixer GEMM (K=2048) + velocity + residual (xnew -> fp16)
    dim3 gD(1024 / 128, MM / 128);
    hgemm<1><<<gD, 256, GEMM_SMEM>>>(p_cc_h, p_wt_h + OFF_OUT,
                                     out_vel, 1024, 2048,
                                     b_out, velocity, x, log_beta, p_xnew_h, nullptr);

    // ffn norm (fp16 in, warp-per-row)
    rmsnorm_h16<<<MM / 8, 256>>>(p_xnew_h, ffn_norm_w, p_nm_h);

    // ff1 + gelu -> fp16 hidden (N=4096, K=1024)
    dim3 gF(4096 / 128, MM / 128);
    hgemm<2><<<gF, 256, GEMM_SMEM>>>(p_nm_h, p_wt_h + OFF_FF1,
                                     nullptr, 4096, 1024,
                                     b_ff1, nullptr, nullptr, nullptr, p_hd_h, nullptr);

    // ff2 + fp16 residual (K=4096) -> out1
    hgemm<3><<<gD, 256, GEMM_SMEM>>>(p_hd_h, p_wt_h + OFF_FF2,
                                     out1, 1024, 4096,
                                     b_ff2, nullptr, nullptr, nullptr, nullptr, p_xnew_h);
}

// round 16
// speedup vs baseline: 1.0335x; 1.0212x over previous
#include <cuda_runtime.h>
#include <cuda_fp16.h>
#include <math.h>
#include <stdint.h>

// ---------------- problem constants ----------------
constexpr int BB = 4, SSEQ = 2048, DD = 1024, FF = 4096;
constexpr int MM = BB * SSEQ;                 // 8192
constexpr long long BSD = (long long)MM * DD; // 8388608

// ---------------- scratch (device globals; no allocation) ----------------
__device__ __half g_xn_h[MM * DD];
__device__ __half g_gate[MM * DD];            // sigmoid(gate_pre), fp16
__device__ __half g_m[MM * DD];               // m = 1 - a, fp16 (bounded-error encoding)
__device__ __half g_cc_h[MM * 2 * DD];        // [conv | griffin_h] fp16
__device__ __half g_xnew_h[MM * DD];          // x + velocity_new, fp16
__device__ __half g_nm_h[MM * DD];
__device__ __half g_hd_h[MM * FF];
__device__ __half g_wt_h[12 * 1024 * 1024];
__device__ float  g_splam[DD];
// decoupled-lookback scan records: 64 chunks x (B*D) channels
constexpr int SCH = 64, SLEN = SSEQ / SCH;    // 64 chunks of 32
__device__ float2 g_recPH[BB * SCH * DD];     // (p, h) partial
__device__ float  g_recI [BB * SCH * DD];     // inclusive H

// ---------------- helpers ----------------
__device__ __forceinline__ uint32_t s2u(const void* p) {
    uint32_t a;
    asm("{ .reg .u64 t; cvta.to.shared.u64 t, %1; cvt.u32.u64 %0, t; }" : "=r"(a) : "l"(p));
    return a;
}
__device__ __forceinline__ void cpasync16(uint32_t saddr, const void* g) {
    asm volatile("cp.async.cg.shared.global [%0], [%1], 16;" :: "r"(saddr), "l"(g));
}
__device__ __forceinline__ void cp_commit() {
    asm volatile("cp.async.commit_group;" ::: "memory");
}
template <int N>
__device__ __forceinline__ void cp_wait() {
    asm volatile("cp.async.wait_group %0;" :: "n"(N) : "memory");
}
__device__ __forceinline__ void ldsm4(uint32_t* r, uint32_t addr) {
    asm volatile("ldmatrix.sync.aligned.m8n8.x4.shared.b16 {%0,%1,%2,%3}, [%4];"
                 : "=r"(r[0]), "=r"(r[1]), "=r"(r[2]), "=r"(r[3]) : "r"(addr));
}
__device__ __forceinline__ void mma16816(float* d, const uint32_t* a, const uint32_t* b) {
    asm volatile(
        "mma.sync.aligned.m16n8k16.row.col.f32.f16.f16.f32 "
        "{%0,%1,%2,%3}, {%4,%5,%6,%7}, {%8,%9}, {%0,%1,%2,%3};"
        : "+f"(d[0]), "+f"(d[1]), "+f"(d[2]), "+f"(d[3])
        : "r"(a[0]), "r"(a[1]), "r"(a[2]), "r"(a[3]), "r"(b[0]), "r"(b[1]));
}
__device__ __forceinline__ float2 ldcg2(const float2* p) {
    float2 v;
    asm volatile("ld.global.cg.v2.f32 {%0,%1}, [%2];" : "=f"(v.x), "=f"(v.y) : "l"(p));
    return v;
}
__device__ __forceinline__ void stcg2(float2* p, float2 v) {
    asm volatile("st.global.cg.v2.f32 [%0], {%1,%2};" :: "l"(p), "f"(v.x), "f"(v.y) : "memory");
}
__device__ __forceinline__ float ldcg1(const float* p) {
    float v;
    asm volatile("ld.global.cg.f32 %0, [%1];" : "=f"(v) : "l"(p));
    return v;
}
__device__ __forceinline__ void stcg1(float* p, float v) {
    asm volatile("st.global.cg.f32 [%0], %1;" :: "l"(p), "f"(v) : "memory");
}
__device__ __forceinline__ uint32_t h2u(__half2 h) {
    return *(uint32_t*)&h;
}

// ------- weight transpose (block-offset param so it can be split) -------
__global__ void transpose_all(const float* __restrict__ Wg, const float* __restrict__ Wa,
                              const float* __restrict__ Wo, const float* __restrict__ W1,
                              const float* __restrict__ W2, __half* __restrict__ out,
                              int boff) {
    int b = blockIdx.x + boff;
    const float* W;
    int K, N;
    size_t off;
    int tile;
    if (b < 1024)      { W = Wg; K = 1024; N = 1024; off = 0;               tile = b; }
    else if (b < 2048) { W = Wa; K = 1024; N = 1024; off = (size_t)1 << 20; tile = b - 1024; }
    else if (b < 4096) { W = Wo; K = 2048; N = 1024; off = (size_t)2 << 20; tile = b - 2048; }
    else if (b < 8192) { W = W1; K = 1024; N = 4096; off = (size_t)4 << 20; tile = b - 4096; }
    else               { W = W2; K = 4096; N = 1024; off = (size_t)8 << 20; tile = b - 8192; }
    int ntn = N >> 5;
    int n0 = (tile % ntn) * 32, k0 = (tile / ntn) * 32;
    __half* oh = out + off;

    __shared__ float t[32][33];
    int tid = threadIdx.x;
    #pragma unroll
    for (int i = 0; i < 4; i++) {
        int idx = tid + i * 256;
        int kr = idx >> 5, nc = idx & 31;
        t[kr][nc] = W[(size_t)(k0 + kr) * N + n0 + nc];
    }
    __syncthreads();
    #pragma unroll
    for (int i = 0; i < 2; i++) {
        int idx = tid + i * 256;
        int nr = idx >> 4, kp = idx & 15;
        float v0 = t[kp * 2][nr], v1 = t[kp * 2 + 1][nr];
        size_t o = (size_t)(n0 + nr) * K + k0 + kp * 2;
        *(__half2*)(oh + o) = __halves2half2(__float2half_rn(v0), __float2half_rn(v1));
    }
}

// ------- rmsnorm (fp32 in) -> fp16, warp-per-row -------
__global__ void __launch_bounds__(256) rmsnorm_h(const float* __restrict__ in,
                                                 const float* __restrict__ w,
                                                 __half* __restrict__ oh) {
    int lane = threadIdx.x & 31, wrp = threadIdx.x >> 5;
    int row = blockIdx.x * 8 + wrp;
    const float4* ip = (const float4*)(in + (size_t)row * DD);
    float4 v[8];
    float ss = 0.f;
    #pragma unroll
    for (int i = 0; i < 8; i++) {
        v[i] = ip[lane + i * 32];
        ss += v[i].x * v[i].x + v[i].y * v[i].y + v[i].z * v[i].z + v[i].w * v[i].w;
    }
    #pragma unroll
    for (int o = 16; o > 0; o >>= 1) ss += __shfl_xor_sync(0xffffffffu, ss, o);
    float rms = rsqrtf(ss * (1.0f / DD) + 1e-6f);
    #pragma unroll
    for (int i = 0; i < 8; i++) {
        float4 wv = ((const float4*)w)[lane + i * 32];
        __half2 h0 = __halves2half2(__float2half_rn(v[i].x * rms * wv.x),
                                    __float2half_rn(v[i].y * rms * wv.y));
        __half2 h1 = __halves2half2(__float2half_rn(v[i].z * rms * wv.z),
                                    __float2half_rn(v[i].w * rms * wv.w));
        *(uint2*)(oh + (size_t)row * DD + (lane + i * 32) * 4) = make_uint2(h2u(h0), h2u(h1));
    }
}

// ------- rmsnorm (fp16 in) -> fp16, warp-per-row -------
__global__ void __launch_bounds__(256) rmsnorm_h16(const __half* __restrict__ in,
                                                   const float* __restrict__ w,
                                                   __half* __restrict__ oh) {
    int lane = threadIdx.x & 31, wrp = threadIdx.x >> 5;
    int row = blockIdx.x * 8 + wrp;
    const float4* ip = (const float4*)(in + (size_t)row * DD);  // 8 halves per float4
    float4 raw[4];
    float xs[32];
    float ss = 0.f;
    #pragma unroll
    for (int i = 0; i < 4; i++) {
        raw[i] = ip[lane + i * 32];
        const __half2* hp = (const __half2*)&raw[i];
        #pragma unroll
        for (int j = 0; j < 4; j++) {
            float2 f = __half22float2(hp[j]);
            xs[i * 8 + j * 2] = f.x;
            xs[i * 8 + j * 2 + 1] = f.y;
            ss += f.x * f.x + f.y * f.y;
        }
    }
    #pragma unroll
    for (int o = 16; o > 0; o >>= 1) ss += __shfl_xor_sync(0xffffffffu, ss, o);
    float rms = rsqrtf(ss * (1.0f / DD) + 1e-6f);
    #pragma unroll
    for (int i = 0; i < 4; i++) {
        int e0 = (lane + i * 32) * 8;
        uint32_t pk[4];
        #pragma unroll
        for (int j = 0; j < 4; j++) {
            float2 wv = ((const float2*)w)[e0 / 2 + j];
            __half2 h = __halves2half2(__float2half_rn(xs[i * 8 + j * 2] * rms * wv.x),
                                       __float2half_rn(xs[i * 8 + j * 2 + 1] * rms * wv.y));
            pk[j] = h2u(h);
        }
        *(uint4*)(oh + (size_t)row * DD + e0) = make_uint4(pk[0], pk[1], pk[2], pk[3]);
    }
}

// ------- prologue: clear lookback records + splam -------
__global__ void prologue(const float* __restrict__ lam) {
    int i = blockIdx.x * 256 + threadIdx.x;   // < BB*SCH*DD = 262144
    float nf = __int_as_float(0x7fffffff);
    g_recPH[i] = make_float2(nf, nf);
    g_recI[i] = nf;
    if (i < DD) {
        float l = lam[i];
        float sp = (l > 20.f) ? l : log1pf(expf(l));
        g_splam[i] = 8.0f * sp;
    }
}

// ------- single-pass scan: conv + u + chunk scan + decoupled lookback -------
// smem stages (m,u) as half2 -> 32 KB/CTA -> ~6 CTAs/SM.
__global__ void __launch_bounds__(256) gscan_one(const float* __restrict__ ck,
                                                 const float* __restrict__ cb) {
    extern __shared__ __half2 au[];           // [SLEN][256] (m, u)
    int tid = threadIdx.x;
    int bid = blockIdx.x;                     // ch*16 + b*4 + dblk
    int ch = bid >> 4;
    int b = (bid >> 2) & 3;
    int dblk = bid & 3;
    int d = dblk * 256 + tid;

    float4 kv = ((const float4*)ck)[d];
    float cbias = cb[d];

    long long r0 = (long long)b * SSEQ + ch * SLEN;
    long long xbase = r0 * DD + d;
    float xm1 = 0.f, xm2 = 0.f, xm3 = 0.f;
    if (ch > 0) {
        xm1 = __half2float(g_xn_h[xbase - DD]);
        xm2 = __half2float(g_xn_h[xbase - 2 * DD]);
        xm3 = __half2float(g_xn_h[xbase - 3 * DD]);
    }
    float p = 1.f, h = 0.f;
    #pragma unroll 4
    for (int t = 0; t < SLEN; t++) {
        long long i = xbase + (long long)t * DD;
        float xn = __half2float(g_xn_h[i]);
        float conv = cbias + kv.x * xn + kv.y * xm1 + kv.z * xm2 + kv.w * xm3;
        float gate = __half2float(g_gate[i]);
        float m = __half2float(g_m[i]);       // m = 1 - a
        float a = 1.f - m;
        float u = sqrtf(fmaxf(m * (2.f - m), 0.f)) * gate * xn;
        g_cc_h[(r0 + t) * (2 * DD) + d] = __float2half_rn(conv);
        au[t * 256 + tid] = __halves2half2(__float2half_rn(m), __float2half_rn(u));
        p *= a;
        h = fmaf(a, h, u);
        xm3 = xm2; xm2 = xm1; xm1 = xn;
    }

    int recbase = b * SCH * DD + d;
    stcg2(&g_recPH[recbase + ch * DD], make_float2(p, h));

    float C = 0.f;
    if (ch > 0) {
        float accP = 1.f, accH = 0.f;
        int look = ch - 1;
        while (true) {
            float hi = ldcg1(&g_recI[recbase + look * DD]);
            if (!isnan(hi)) { C = fmaf(accP, hi, accH); break; }
            float2 ph = ldcg2(&g_recPH[recbase + look * DD]);
            if (!isnan(ph.x)) {
                accH = fmaf(accP, ph.y, accH);
                accP *= ph.x;
                if (--look < 0) { C = accH; break; }
            }
        }
    }
    stcg1(&g_recI[recbase + ch * DD], fmaf(p, C, h));

    h = C;
    #pragma unroll 4
    for (int t = 0; t < SLEN; t++) {
        __half2 v = au[t * 256 + tid];
        float m = __half2float(v.x);
        float u = __half2float(v.y);
        h = fmaf(1.f - m, h, u);
        g_cc_h[(r0 + t) * (2 * DD) + DD + d] = __float2half_rn(h);
    }
}

// ------- HMMA GEMM: 128x128 tile, 8 warps, 64x32 warp tiles, BK=64 -------
// 3-stage cp.async (32 KB/stage), 2 CTAs/SM. grid: x = N-blocks, y = M-blocks.
// EPI: 1 mixer (xnew -> fp16 out2h); 2 gelu->fp16; 3 +bias + fp16 aux residual;
//      4 gating (gate->fp16 auxh, m=1-__expf(-splam*sigmoid)->fp16 out2h, N-stride 1024)
constexpr int STG = 32768;           // A 16K | B 16K
constexpr int GEMM_SMEM = 3 * STG;   // 96 KB

template <int EPI>
__global__ void __launch_bounds__(256)
hgemm(const __half* __restrict__ Ah, const __half* __restrict__ Bh,
      float* __restrict__ C, int N, int K,
      const float* __restrict__ bias,
      const float* __restrict__ aux1, const float* __restrict__ aux2,
      const float* __restrict__ aux3,
      __half* __restrict__ out2h,
      __half* __restrict__ auxh) {
    extern __shared__ char sm[];
    uint32_t sb = s2u(sm);
    int tid = threadIdx.x;
    int lane = tid & 31, wid = tid >> 5;
    int wm = wid >> 2, wn = wid & 3;          // warp tile 64x32
    size_t mrow0 = (size_t)blockIdx.y * 128;
    size_t ncol0 = (size_t)blockIdx.x * 128;

    float acc[4][4][4];
    #pragma unroll
    for (int a = 0; a < 4; a++)
        #pragma unroll
        for (int b = 0; b < 4; b++)
            #pragma unroll
            for (int c = 0; c < 4; c++) acc[a][b][c] = 0.f;

    auto load_stage = [&](int s, int k0) {
        uint32_t base = sb + s * STG;
        #pragma unroll
        for (int i = 0; i < 4; i++) {
            int idx = tid + i * 256;
            int r = idx >> 3, c = idx & 7;
            uint32_t sw = r * 128 + ((c ^ (r & 7)) << 4);
            cpasync16(base + sw, Ah + (mrow0 + r) * K + k0 + c * 8);
            cpasync16(base + 16384 + sw, Bh + (ncol0 + r) * K + k0 + c * 8);
        }
    };

    const int KT = K >> 6;  // BK = 64
    load_stage(0, 0);
    cp_commit();
    load_stage(1, 64);
    cp_commit();

    for (int kt = 0; kt < KT; kt++) {
        if (kt + 1 < KT) cp_wait<1>(); else cp_wait<0>();
        __syncthreads();
        if (kt + 2 < KT) {
            int s = kt + 2;
            load_stage(s % 3, s << 6);
            cp_commit();
        }
        uint32_t base = sb + (kt % 3) * STG;
        #pragma unroll
        for (int kk = 0; kk < 4; kk++) {
            uint32_t ah[4][4], bh[2][4];
            int g = lane >> 3;
            int ar = (lane & 7) + ((g & 1) << 3);
            int ac = kk * 2 + (g >> 1);
            #pragma unroll
            for (int mi = 0; mi < 4; mi++) {
                int row = wm * 64 + mi * 16 + ar;
                uint32_t off = row * 128 + ((ac ^ (row & 7)) << 4);
                ldsm4(ah[mi], base + off);
            }
            int br = (lane & 7) + ((g >> 1) << 3);
            int bc = kk * 2 + (g & 1);
            #pragma unroll
            for (int ni = 0; ni < 2; ni++) {
                int row = wn * 32 + ni * 16 + br;
                uint32_t off = row * 128 + ((bc ^ (row & 7)) << 4);
                ldsm4(bh[ni], base + 16384 + off);
            }
            #pragma unroll
            for (int mi = 0; mi < 4; mi++)
                #pragma unroll
                for (int n8 = 0; n8 < 4; n8++)
                    mma16816(acc[mi][n8], ah[mi], &bh[n8 >> 1][(n8 & 1) * 2]);
        }
    }

    // ---------------- epilogue ----------------
    const float c0g = 0.7978845608028654f, c1g = 0.044715f;
    #pragma unroll
    for (int mi = 0; mi < 4; mi++) {
        #pragma unroll
        for (int n8 = 0; n8 < 4; n8++) {
            int col = (int)ncol0 + wn * 32 + n8 * 8 + (lane & 3) * 2;
            #pragma unroll
            for (int half_ = 0; half_ < 2; half_++) {
                size_t row = mrow0 + wm * 64 + mi * 16 + (lane >> 2) + half_ * 8;
                float v0 = acc[mi][n8][half_ * 2 + 0];
                float v1 = acc[mi][n8][half_ * 2 + 1];
                size_t off = row * N + col;
                if (EPI == 1) {
                    float2 bia = *(const float2*)(bias + col);
                    float2 lb  = *(const float2*)(aux3 + col);
                    float2 vel = *(const float2*)(aux1 + off);
                    float2 xv  = *(const float2*)(aux2 + off);
                    float vn0 = fmaf(1.f / (1.f + __expf(-lb.x)), vel.x, v0 + bia.x);
                    float vn1 = fmaf(1.f / (1.f + __expf(-lb.y)), vel.y, v1 + bia.y);
                    *(float2*)(C + off) = make_float2(vn0, vn1);
                    *(__half2*)(out2h + off) =
                        __halves2half2(__float2half_rn(xv.x + vn0), __float2half_rn(xv.y + vn1));
                } else if (EPI == 2) {
                    float2 bia = *(const float2*)(bias + col);
                    float t0 = v0 + bia.x, t1 = v1 + bia.y;
                    t0 = 0.5f * t0 * (1.f + tanhf(c0g * (t0 + c1g * t0 * t0 * t0)));
                    t1 = 0.5f * t1 * (1.f + tanhf(c0g * (t1 + c1g * t1 * t1 * t1)));
                    *(__half2*)(out2h + off) =
                        __halves2half2(__float2half_rn(t0), __float2half_rn(t1));
                } else if (EPI == 3) {
                    float2 bia = *(const float2*)(bias + col);
                    __half2 xn2 = *(const __half2*)(auxh + off);
                    *(float2*)(C + off) = make_float2(v0 + bia.x + __half2float(xn2.x),
                                                      v1 + bia.y + __half2float(xn2.y));
                } else {  // EPI == 4: gating. N==2048; tile stays in one half.
                    if (col < 1024) {
                        float s0 = 1.f / (1.f + __expf(-v0));
                        float s1 = 1.f / (1.f + __expf(-v1));
                        *(__half2*)(auxh + row * 1024 + col) =
                            __halves2half2(__float2half_rn(s0), __float2half_rn(s1));
                    } else {
                        int d = col - 1024;
                        float sp0 = aux3[d], sp1 = aux3[d + 1];
                        float sa0 = 1.f / (1.f + __expf(-v0));
                        float sa1 = 1.f / (1.f + __expf(-v1));
                        float m0 = 1.f - __expf(-sp0 * sa0);   // m = 1 - a
                        float m1 = 1.f - __expf(-sp1 * sa1);
                        *(__half2*)(out2h + row * 1024 + d) =
                            __halves2half2(__float2half_rn(m0), __float2half_rn(m1));
                    }
                }
            }
        }
    }
}

// ---------------- launch ----------------
extern "C" void kernel_launch(void* const* d_in, const int* in_sizes, int n_in,
                              void* d_out, int out_size) {
    const float* x          = (const float*)d_in[0];
    const float* velocity   = (const float*)d_in[1];
    const float* pre_norm_w = (const float*)d_in[2];
    const float* conv_k     = (const float*)d_in[3];
    const float* conv_b     = (const float*)d_in[4];
    const float* W_gate     = (const float*)d_in[5];
    const float* W_a        = (const float*)d_in[6];
    const float* lam        = (const float*)d_in[7];
    const float* W_out      = (const float*)d_in[8];
    const float* b_out      = (const float*)d_in[9];
    const float* log_beta   = (const float*)d_in[10];
    const float* ffn_norm_w = (const float*)d_in[11];
    const float* W_ff1      = (const float*)d_in[12];
    const float* b_ff1      = (const float*)d_in[13];
    const float* W_ff2      = (const float*)d_in[14];
    const float* b_ff2      = (const float*)d_in[15];

    float* out1    = (float*)d_out;
    float* out_vel = out1 + BSD;

    __half *p_xn_h, *p_gate, *p_m, *p_cc_h, *p_xnew_h, *p_nm_h, *p_hd_h, *p_wt_h;
    float *p_splam;
    cudaGetSymbolAddress((void**)&p_xn_h, g_xn_h);
    cudaGetSymbolAddress((void**)&p_gate, g_gate);
    cudaGetSymbolAddress((void**)&p_m, g_m);
    cudaGetSymbolAddress((void**)&p_cc_h, g_cc_h);
    cudaGetSymbolAddress((void**)&p_xnew_h, g_xnew_h);
    cudaGetSymbolAddress((void**)&p_nm_h, g_nm_h);
    cudaGetSymbolAddress((void**)&p_hd_h, g_hd_h);
    cudaGetSymbolAddress((void**)&p_wt_h, g_wt_h);
    cudaGetSymbolAddress((void**)&p_splam, g_splam);

    cudaFuncSetAttribute(hgemm<1>, cudaFuncAttributeMaxDynamicSharedMemorySize, GEMM_SMEM);
    cudaFuncSetAttribute(hgemm<2>, cudaFuncAttributeMaxDynamicSharedMemorySize, GEMM_SMEM);
    cudaFuncSetAttribute(hgemm<3>, cudaFuncAttributeMaxDynamicSharedMemorySize, GEMM_SMEM);
    cudaFuncSetAttribute(hgemm<4>, cudaFuncAttributeMaxDynamicSharedMemorySize, GEMM_SMEM);
    constexpr int SCAN_SMEM = SLEN * 256 * sizeof(__half2);   // 32 KB
    cudaFuncSetAttribute(gscan_one, cudaFuncAttributeMaxDynamicSharedMemorySize, SCAN_SMEM);

    // side stream + fork/join events
    cudaStream_t s_side;
    cudaEvent_t ev_fork, ev_j1, ev_j2;
    cudaStreamCreateWithFlags(&s_side, cudaStreamNonBlocking);
    cudaEventCreateWithFlags(&ev_fork, cudaEventDisableTiming);
    cudaEventCreateWithFlags(&ev_j1, cudaEventDisableTiming);
    cudaEventCreateWithFlags(&ev_j2, cudaEventDisableTiming);

    const size_t OFF_GA = 0, OFF_OUT = (size_t)2 << 20,
                 OFF_FF1 = (size_t)4 << 20, OFF_FF2 = (size_t)8 << 20;

    // fork side branch: weight transposes
    cudaEventRecord(ev_fork, 0);
    cudaStreamWaitEvent(s_side, ev_fork, 0);
    transpose_all<<<2048, 256, 0, s_side>>>(W_gate, W_a, W_out, W_ff1, W_ff2, p_wt_h, 0);
    cudaEventRecord(ev_j1, s_side);
    transpose_all<<<10240, 256, 0, s_side>>>(W_gate, W_a, W_out, W_ff1, W_ff2, p_wt_h, 2048);
    cudaEventRecord(ev_j2, s_side);

    // main stream: pre-norm (warp-per-row) + prologue
    rmsnorm_h<<<MM / 8, 256>>>(x, pre_norm_w, p_xn_h);
    prologue<<<BB * SCH * DD / 256, 256>>>(lam);

    // join 1: gate/a weights ready
    cudaStreamWaitEvent(0, ev_j1, 0);

    // fused gate+a GEMM (M=8192, N=2048, K=1024) with gating epilogue
    dim3 gGA(2048 / 128, MM / 128);
    hgemm<4><<<gGA, 256, GEMM_SMEM>>>(p_xn_h, p_wt_h + OFF_GA,
                                      nullptr, 2048, 1024,
                                      nullptr, nullptr, nullptr, p_splam, p_m, p_gate);

    // single-pass conv + gating + scan (decoupled lookback)
    gscan_one<<<BB * SCH * (DD / 256), 256, SCAN_SMEM>>>(conv_k, conv_b);

    // join 2: remaining weights ready
    cudaStreamWaitEvent(0, ev_j2, 0);

    // mixer GEMM (K=2048) + velocity + residual (xnew -> fp16)
    dim3 gD(1024 / 128, MM / 128);
    hgemm<1><<<gD, 256, GEMM_SMEM>>>(p_cc_h, p_wt_h + OFF_OUT,
                                     out_vel, 1024, 2048,
                                     b_out, velocity, x, log_beta, p_xnew_h, nullptr);

    // ffn norm (fp16 in, warp-per-row)
    rmsnorm_h16<<<MM / 8, 256>>>(p_xnew_h, ffn_norm_w, p_nm_h);

    // ff1 + gelu -> fp16 hidden (N=4096, K=1024)
    dim3 gF(4096 / 128, MM / 128);
    hgemm<2><<<gF, 256, GEMM_SMEM>>>(p_nm_h, p_wt_h + OFF_FF1,
                                     nullptr, 4096, 1024,
                                     b_ff1, nullptr, nullptr, nullptr, p_hd_h, nullptr);

    // ff2 + fp16 residual (K=4096) -> out1
    hgemm<3><<<gD, 256, GEMM_SMEM>>>(p_hd_h, p_wt_h + OFF_FF2,
                                     out1, 1024, 4096,
                                     b_ff2, nullptr, nullptr, nullptr, nullptr, p_xnew_h);
}